// round 5
// baseline (speedup 1.0000x reference)
#include <cuda_runtime.h>
#include <float.h>

// ChamferLossKL: bs=8, n=2048, d=4.
// t_ij = S_ij + csb_j + ca_i = 2*KL_ij + 4, computed ONCE per pair.
//   S = sum_d A_id*iv_jd + sum_d mu_id*w_jd
//   A = exp(la)+mu_a^2, ca = -sum(la); iv = exp(-lb), w = -2*mu_b*iv,
//   csb = sum(mu_b^2*iv) + sum(lb)
// rowres_i = 0.5*min_j t - 2 ; colres_j = 0.5*min_i t - 2
// loss_b = 0.5*(sum_i min_j t + sum_j min_i t) - 2*(2*NP)
// Mins via order-preserving uint keys -> redux.sync.umin + global atomicMin.

#define NB 8
#define NP 2048
#define ITILE 128
#define NITILE 16
#define CHJ 256
#define CHP 128
#define NCH 8

typedef unsigned long long ull;

// ---- packed f32x2 helpers ----
__device__ __forceinline__ ull ffma2(ull a, ull b, ull c) {
    ull d; asm("fma.rn.f32x2 %0, %1, %2, %3;" : "=l"(d) : "l"(a), "l"(b), "l"(c));
    return d;
}
__device__ __forceinline__ ull fadd2(ull a, ull b) {
    ull d; asm("add.rn.f32x2 %0, %1, %2;" : "=l"(d) : "l"(a), "l"(b));
    return d;
}
__device__ __forceinline__ ull packdup(float x) {
    ull d; asm("mov.b64 %0, {%1, %1};" : "=l"(d) : "f"(x));
    return d;
}
__device__ __forceinline__ void unpk(ull v, float& lo, float& hi) {
    asm("mov.b64 {%0, %1}, %2;" : "=f"(lo), "=f"(hi) : "l"(v));
}
__device__ __forceinline__ void lds_v2(ull& a, ull& b, unsigned int addr) {
    asm volatile("ld.shared.v2.u64 {%0, %1}, [%2];" : "=l"(a), "=l"(b) : "r"(addr));
}
__device__ __forceinline__ ull lds_1(unsigned int addr) {
    ull a; asm volatile("ld.shared.u64 %0, [%1];" : "=l"(a) : "r"(addr));
    return a;
}

// order-preserving float -> uint key (exact)
__device__ __forceinline__ unsigned int skey(float f) {
    unsigned int u = __float_as_uint(f);
    return u ^ ((unsigned int)((int)u >> 31) | 0x80000000u);
}
__device__ __forceinline__ float unkey(unsigned int u) {
    unsigned int b = u ^ ((unsigned int)((int)(~u) >> 31) | 0x80000000u);
    return __uint_as_float(b);
}

// ---- scratch ----
__device__ unsigned int g_rowmin[NB * NP];
__device__ unsigned int g_colmin[NB * NP];

__global__ void ck_init() {
    int idx = blockIdx.x * blockDim.x + threadIdx.x;
    if (idx < NB * NP) {
        g_rowmin[idx] = 0xFFFFFFFFu;
        g_colmin[idx] = 0xFFFFFFFFu;
    }
}

// grid (NITILE, NB, NCH) = 1024 CTAs, 128 threads.
__global__ __launch_bounds__(128) void ck_main(const float* __restrict__ mu_p,
                                               const float* __restrict__ lv_p,
                                               const float* __restrict__ mu_g,
                                               const float* __restrict__ lv_g) {
    __shared__ float4 s_stream[CHP * 5];  // 128 pairs * 80B = 10 KB
    __shared__ uint2  s_col[4 * CHP];     // 4 KB

    int tid  = threadIdx.x;
    int lane = tid & 31;
    int w    = tid >> 5;
    int b     = blockIdx.y;
    int itile = blockIdx.x;
    int ch    = blockIdx.z;

    // self coefficients (preds)
    int i = itile * ITILE + tid;
    float4 mp = reinterpret_cast<const float4*>(mu_p)[b * NP + i];
    float4 lp = reinterpret_cast<const float4*>(lv_p)[b * NP + i];
    float Ax = expf(lp.x) + mp.x * mp.x;
    float Ay = expf(lp.y) + mp.y * mp.y;
    float Az = expf(lp.z) + mp.z * mp.z;
    float Aw = expf(lp.w) + mp.w * mp.w;
    float ca = -(lp.x + lp.y + lp.z + lp.w);
    ull cA0 = packdup(Ax), cA1 = packdup(Ay), cA2 = packdup(Az), cA3 = packdup(Aw);
    ull cM0 = packdup(mp.x), cM1 = packdup(mp.y), cM2 = packdup(mp.z), cM3 = packdup(mp.w);
    ull ca2 = packdup(ca);

    // stream prep (gts): thread t builds pair t of this chunk
    {
        int j0 = ch * CHJ + 2 * tid;
        float4 mg0 = reinterpret_cast<const float4*>(mu_g)[b * NP + j0];
        float4 lg0 = reinterpret_cast<const float4*>(lv_g)[b * NP + j0];
        float4 mg1 = reinterpret_cast<const float4*>(mu_g)[b * NP + j0 + 1];
        float4 lg1 = reinterpret_cast<const float4*>(lv_g)[b * NP + j0 + 1];
        float4 iv0, iv1, w0, w1;
        iv0.x = expf(-lg0.x); iv0.y = expf(-lg0.y); iv0.z = expf(-lg0.z); iv0.w = expf(-lg0.w);
        iv1.x = expf(-lg1.x); iv1.y = expf(-lg1.y); iv1.z = expf(-lg1.z); iv1.w = expf(-lg1.w);
        w0.x = -2.f * mg0.x * iv0.x; w0.y = -2.f * mg0.y * iv0.y;
        w0.z = -2.f * mg0.z * iv0.z; w0.w = -2.f * mg0.w * iv0.w;
        w1.x = -2.f * mg1.x * iv1.x; w1.y = -2.f * mg1.y * iv1.y;
        w1.z = -2.f * mg1.z * iv1.z; w1.w = -2.f * mg1.w * iv1.w;
        float csb0 = mg0.x * mg0.x * iv0.x + mg0.y * mg0.y * iv0.y
                   + mg0.z * mg0.z * iv0.z + mg0.w * mg0.w * iv0.w
                   + lg0.x + lg0.y + lg0.z + lg0.w;
        float csb1 = mg1.x * mg1.x * iv1.x + mg1.y * mg1.y * iv1.y
                   + mg1.z * mg1.z * iv1.z + mg1.w * mg1.w * iv1.w
                   + lg1.x + lg1.y + lg1.z + lg1.w;
        s_stream[tid * 5 + 0] = make_float4(iv0.x, iv1.x, iv0.y, iv1.y);
        s_stream[tid * 5 + 1] = make_float4(iv0.z, iv1.z, iv0.w, iv1.w);
        s_stream[tid * 5 + 2] = make_float4(w0.x, w1.x, w0.y, w1.y);
        s_stream[tid * 5 + 3] = make_float4(w0.z, w1.z, w0.w, w1.w);
        s_stream[tid * 5 + 4] = make_float4(csb0, csb1, 0.f, 0.f);
    }
    __syncthreads();

    unsigned int sbase = (unsigned int)__cvta_generic_to_shared(s_stream);
    float minr0 = FLT_MAX, minr1 = FLT_MAX;

    unsigned int ad = sbase;
#pragma unroll 8
    for (int p = 0; p < CHP; p++) {
        ull q0, q1, q2, q3, r0, r1, r2, r3;
        lds_v2(q0, q1, ad);
        lds_v2(q2, q3, ad + 16);
        lds_v2(r0, r1, ad + 32);
        lds_v2(r2, r3, ad + 48);
        ull csb = lds_1(ad + 64);
        ull acc = ffma2(cA0, q0, ca2);     // seed with per-i constant
        acc = ffma2(cA1, q1, acc);
        acc = ffma2(cA2, q2, acc);
        acc = ffma2(cA3, q3, acc);
        acc = ffma2(cM0, r0, acc);
        acc = ffma2(cM1, r1, acc);
        acc = ffma2(cM2, r2, acc);
        acc = ffma2(cM3, r3, acc);
        ull t = fadd2(acc, csb);           // t = 2*KL + 4 for (j0, j1)
        float tlo, thi; unpk(t, tlo, thi);
        minr0 = fminf(minr0, tlo);
        minr1 = fminf(minr1, thi);
        unsigned int klo = __reduce_min_sync(0xffffffffu, skey(tlo));
        unsigned int khi = __reduce_min_sync(0xffffffffu, skey(thi));
        if (lane == 0) s_col[w * CHP + p] = make_uint2(klo, khi);
        ad += 80;
    }

    // row min -> global atomicMin
    atomicMin(&g_rowmin[b * NP + i], skey(fminf(minr0, minr1)));

    __syncthreads();
    // combine 4 warps' col mins, one RED per j
    {
        uint2 m0 = s_col[tid], m1 = s_col[CHP + tid];
        uint2 m2 = s_col[2 * CHP + tid], m3 = s_col[3 * CHP + tid];
        unsigned int mx = min(min(m0.x, m1.x), min(m2.x, m3.x));
        unsigned int my = min(min(m0.y, m1.y), min(m2.y, m3.y));
        int j0 = ch * CHJ + 2 * tid;
        atomicMin(&g_colmin[b * NP + j0], mx);
        atomicMin(&g_colmin[b * NP + j0 + 1], my);
    }
}

// grid NB, 256 threads
__global__ __launch_bounds__(256) void ck_reduce(float* __restrict__ out) {
    int b = blockIdx.x;
    int tid = threadIdx.x;
    float sum = 0.f;
#pragma unroll
    for (int k = tid; k < NP; k += 256)
        sum += unkey(g_rowmin[b * NP + k]) + unkey(g_colmin[b * NP + k]);
    __shared__ float red[256];
    red[tid] = sum;
    __syncthreads();
    for (int st = 128; st > 0; st >>= 1) {
        if (tid < st) red[tid] += red[tid + st];
        __syncthreads();
    }
    if (tid == 0) out[b] = 0.5f * red[0] - 2.0f * (2.0f * NP);
}

extern "C" void kernel_launch(void* const* d_in, const int* in_sizes, int n_in,
                              void* d_out, int out_size) {
    const float* mu_p = (const float*)d_in[0];
    const float* lv_p = (const float*)d_in[1];
    const float* mu_g = (const float*)d_in[2];
    const float* lv_g = (const float*)d_in[3];
    float* out = (float*)d_out;

    ck_init<<<(NB * NP + 255) / 256, 256>>>();

    dim3 grid(NITILE, NB, NCH);  // 1024 CTAs
    ck_main<<<grid, 128>>>(mu_p, lv_p, mu_g, lv_g);

    ck_reduce<<<NB, 256>>>(out);
}

// round 7
// speedup vs baseline: 1.0725x; 1.0725x over previous
#include <cuda_runtime.h>
#include <float.h>

// ChamferLossKL: bs=8, n=2048, d=4.
// t_ij = S_ij + csb_j + ca_i = 2*KL_ij + 4, computed ONCE per pair.
//   S = sum_d A_id*iv_jd + sum_d mu_id*w_jd
//   A = exp(la)+mu_a^2, ca = -sum(la); iv = exp(-lb), w = -2*mu_b*iv,
//   csb = sum(mu_b^2*iv) + sum(lb)
// loss_b = 0.5*(sum_i min_j t + sum_j min_i t) - 4*NP
// Each thread: 2 i-chains x 2 packed j per iteration = 4 pairs/lane/iter.
// Cross-lane col-min via redux.sync.umin on order-preserving uint keys.

#define NB 8
#define NP 2048
#define ITILE 256           // i per CTA (2 per thread)
#define NITILE 8
#define CHJ 256             // j per CTA
#define CHP 128             // j-pairs per CTA
#define NCH 8

typedef unsigned long long ull;

__device__ __forceinline__ ull ffma2(ull a, ull b, ull c) {
    ull d; asm("fma.rn.f32x2 %0, %1, %2, %3;" : "=l"(d) : "l"(a), "l"(b), "l"(c));
    return d;
}
__device__ __forceinline__ ull fadd2(ull a, ull b) {
    ull d; asm("add.rn.f32x2 %0, %1, %2;" : "=l"(d) : "l"(a), "l"(b));
    return d;
}
__device__ __forceinline__ ull packdup(float x) {
    ull d; asm("mov.b64 %0, {%1, %1};" : "=l"(d) : "f"(x));
    return d;
}
__device__ __forceinline__ void unpk(ull v, float& lo, float& hi) {
    asm("mov.b64 {%0, %1}, %2;" : "=f"(lo), "=f"(hi) : "l"(v));
}
__device__ __forceinline__ void lds_v2(ull& a, ull& b, unsigned int addr) {
    asm volatile("ld.shared.v2.u64 {%0, %1}, [%2];" : "=l"(a), "=l"(b) : "r"(addr));
}
__device__ __forceinline__ ull lds_1(unsigned int addr) {
    ull a; asm volatile("ld.shared.u64 %0, [%1];" : "=l"(a) : "r"(addr));
    return a;
}
// order-preserving float<->uint keys (exact, total order)
__device__ __forceinline__ unsigned int skey(float f) {
    unsigned int u = __float_as_uint(f);
    return u ^ ((unsigned int)((int)u >> 31) | 0x80000000u);
}
__device__ __forceinline__ float unkey(unsigned int u) {
    unsigned int b = u ^ ((unsigned int)((int)(~u) >> 31) | 0x80000000u);
    return __uint_as_float(b);
}
__device__ __forceinline__ unsigned int redux_umin(unsigned int v) {
    unsigned int r;
    asm("redux.sync.min.u32 %0, %1, 0xffffffff;" : "=r"(r) : "r"(v));
    return r;
}

// ---- scratch (written fully each call; no init needed) ----
__device__ float  g_rowpart[NB * NCH * NP];          // 512 KB
__device__ float2 g_colpart[NB * NITILE * (NP / 2)]; // 512 KB

// grid (NITILE, NB, NCH) = 512 CTAs, 128 threads.
__global__ __launch_bounds__(128) void ck_main(const float* __restrict__ mu_p,
                                               const float* __restrict__ lv_p,
                                               const float* __restrict__ mu_g,
                                               const float* __restrict__ lv_g) {
    __shared__ float4 s_stream[CHP * 5];  // 10 KB
    __shared__ uint2  s_col[4 * CHP];     // 4 KB

    int tid  = threadIdx.x;
    int lane = tid & 31;
    int w    = tid >> 5;
    int b     = blockIdx.y;
    int itile = blockIdx.x;
    int ch    = blockIdx.z;

    // ---- self coefficients: two i per thread ----
    int ia = itile * ITILE + tid;
    int ib = ia + 128;
    float4 mpa = reinterpret_cast<const float4*>(mu_p)[b * NP + ia];
    float4 lpa = reinterpret_cast<const float4*>(lv_p)[b * NP + ia];
    float4 mpb = reinterpret_cast<const float4*>(mu_p)[b * NP + ib];
    float4 lpb = reinterpret_cast<const float4*>(lv_p)[b * NP + ib];

    float caa = -(lpa.x + lpa.y + lpa.z + lpa.w);
    float cab = -(lpb.x + lpb.y + lpb.z + lpb.w);
    ull aA0 = packdup(expf(lpa.x) + mpa.x * mpa.x);
    ull aA1 = packdup(expf(lpa.y) + mpa.y * mpa.y);
    ull aA2 = packdup(expf(lpa.z) + mpa.z * mpa.z);
    ull aA3 = packdup(expf(lpa.w) + mpa.w * mpa.w);
    ull aM0 = packdup(mpa.x), aM1 = packdup(mpa.y), aM2 = packdup(mpa.z), aM3 = packdup(mpa.w);
    ull aC  = packdup(caa);
    ull bA0 = packdup(expf(lpb.x) + mpb.x * mpb.x);
    ull bA1 = packdup(expf(lpb.y) + mpb.y * mpb.y);
    ull bA2 = packdup(expf(lpb.z) + mpb.z * mpb.z);
    ull bA3 = packdup(expf(lpb.w) + mpb.w * mpb.w);
    ull bM0 = packdup(mpb.x), bM1 = packdup(mpb.y), bM2 = packdup(mpb.z), bM3 = packdup(mpb.w);
    ull bC  = packdup(cab);

    // ---- stream prep (gts): thread t builds j-pair t ----
    {
        int j0 = ch * CHJ + 2 * tid;
        float4 mg0 = reinterpret_cast<const float4*>(mu_g)[b * NP + j0];
        float4 lg0 = reinterpret_cast<const float4*>(lv_g)[b * NP + j0];
        float4 mg1 = reinterpret_cast<const float4*>(mu_g)[b * NP + j0 + 1];
        float4 lg1 = reinterpret_cast<const float4*>(lv_g)[b * NP + j0 + 1];
        float4 iv0, iv1, w0, w1;
        iv0.x = expf(-lg0.x); iv0.y = expf(-lg0.y); iv0.z = expf(-lg0.z); iv0.w = expf(-lg0.w);
        iv1.x = expf(-lg1.x); iv1.y = expf(-lg1.y); iv1.z = expf(-lg1.z); iv1.w = expf(-lg1.w);
        w0.x = -2.f * mg0.x * iv0.x; w0.y = -2.f * mg0.y * iv0.y;
        w0.z = -2.f * mg0.z * iv0.z; w0.w = -2.f * mg0.w * iv0.w;
        w1.x = -2.f * mg1.x * iv1.x; w1.y = -2.f * mg1.y * iv1.y;
        w1.z = -2.f * mg1.z * iv1.z; w1.w = -2.f * mg1.w * iv1.w;
        float csb0 = mg0.x * mg0.x * iv0.x + mg0.y * mg0.y * iv0.y
                   + mg0.z * mg0.z * iv0.z + mg0.w * mg0.w * iv0.w
                   + lg0.x + lg0.y + lg0.z + lg0.w;
        float csb1 = mg1.x * mg1.x * iv1.x + mg1.y * mg1.y * iv1.y
                   + mg1.z * mg1.z * iv1.z + mg1.w * mg1.w * iv1.w
                   + lg1.x + lg1.y + lg1.z + lg1.w;
        s_stream[tid * 5 + 0] = make_float4(iv0.x, iv1.x, iv0.y, iv1.y);
        s_stream[tid * 5 + 1] = make_float4(iv0.z, iv1.z, iv0.w, iv1.w);
        s_stream[tid * 5 + 2] = make_float4(w0.x, w1.x, w0.y, w1.y);
        s_stream[tid * 5 + 3] = make_float4(w0.z, w1.z, w0.w, w1.w);
        s_stream[tid * 5 + 4] = make_float4(csb0, csb1, 0.f, 0.f);
    }
    __syncthreads();

    unsigned int sbase = (unsigned int)__cvta_generic_to_shared(s_stream);
    float minA0 = FLT_MAX, minA1 = FLT_MAX;
    float minB0 = FLT_MAX, minB1 = FLT_MAX;

    unsigned int ad = sbase;
#pragma unroll 4
    for (int p = 0; p < CHP; p++) {
        ull q0, q1, q2, q3, r0, r1, r2, r3;
        lds_v2(q0, q1, ad);
        lds_v2(q2, q3, ad + 16);
        lds_v2(r0, r1, ad + 32);
        lds_v2(r2, r3, ad + 48);
        ull csb = lds_1(ad + 64);

        ull sa = ffma2(aA0, q0, aC);
        ull sb = ffma2(bA0, q0, bC);
        sa = ffma2(aA1, q1, sa);  sb = ffma2(bA1, q1, sb);
        sa = ffma2(aA2, q2, sa);  sb = ffma2(bA2, q2, sb);
        sa = ffma2(aA3, q3, sa);  sb = ffma2(bA3, q3, sb);
        sa = ffma2(aM0, r0, sa);  sb = ffma2(bM0, r0, sb);
        sa = ffma2(aM1, r1, sa);  sb = ffma2(bM1, r1, sb);
        sa = ffma2(aM2, r2, sa);  sb = ffma2(bM2, r2, sb);
        sa = ffma2(aM3, r3, sa);  sb = ffma2(bM3, r3, sb);
        ull ta = fadd2(sa, csb);
        ull tb = fadd2(sb, csb);

        float ta0, ta1, tb0, tb1;
        unpk(ta, ta0, ta1);
        unpk(tb, tb0, tb1);
        minA0 = fminf(minA0, ta0); minA1 = fminf(minA1, ta1);
        minB0 = fminf(minB0, tb0); minB1 = fminf(minB1, tb1);

        unsigned int c0 = redux_umin(skey(fminf(ta0, tb0)));
        unsigned int c1 = redux_umin(skey(fminf(ta1, tb1)));
        if (lane == 0) s_col[w * CHP + p] = make_uint2(c0, c1);
        ad += 80;
    }

    // row partials (no init needed: unique slots)
    g_rowpart[(b * NCH + ch) * NP + ia] = fminf(minA0, minA1);
    g_rowpart[(b * NCH + ch) * NP + ib] = fminf(minB0, minB1);

    __syncthreads();
    {
        uint2 m0 = s_col[tid], m1 = s_col[CHP + tid];
        uint2 m2 = s_col[2 * CHP + tid], m3 = s_col[3 * CHP + tid];
        unsigned int mx = min(min(m0.x, m1.x), min(m2.x, m3.x));
        unsigned int my = min(min(m0.y, m1.y), min(m2.y, m3.y));
        g_colpart[(b * NITILE + itile) * (NP / 2) + ch * CHP + tid] =
            make_float2(unkey(mx), unkey(my));
    }
}

// grid NB = 8 CTAs, 512 threads. Reads 128 KB/CTA from L2.
__global__ __launch_bounds__(512) void ck_reduce(float* __restrict__ out) {
    int b = blockIdx.x;
    int tid = threadIdx.x;
    float sum = 0.f;

    // rows: min over NCH chunk partials (8 independent LDGs each)
    const float* rp = &g_rowpart[b * NCH * NP];
#pragma unroll
    for (int k = 0; k < NP / 512; k++) {
        int i = k * 512 + tid;
        float v = rp[i];
#pragma unroll
        for (int c = 1; c < NCH; c++) v = fminf(v, rp[c * NP + i]);
        sum += v;
    }
    // cols: min over NITILE tile partials
    const float2* cp = &g_colpart[b * NITILE * (NP / 2)];
#pragma unroll
    for (int k = 0; k < (NP / 2) / 512; k++) {
        int e = k * 512 + tid;
        float2 m = cp[e];
#pragma unroll
        for (int it = 1; it < NITILE; it++) {
            float2 v = cp[it * (NP / 2) + e];
            m.x = fminf(m.x, v.x);
            m.y = fminf(m.y, v.y);
        }
        sum += m.x + m.y;
    }

    __shared__ float red[512];
    red[tid] = sum;
    __syncthreads();
    for (int st = 256; st > 0; st >>= 1) {
        if (tid < st) red[tid] += red[tid + st];
        __syncthreads();
    }
    if (tid == 0) out[b] = 0.5f * red[0] - 2.0f * (2.0f * NP);
}

extern "C" void kernel_launch(void* const* d_in, const int* in_sizes, int n_in,
                              void* d_out, int out_size) {
    const float* mu_p = (const float*)d_in[0];
    const float* lv_p = (const float*)d_in[1];
    const float* mu_g = (const float*)d_in[2];
    const float* lv_g = (const float*)d_in[3];
    float* out = (float*)d_out;

    dim3 grid(NITILE, NB, NCH);  // 8 x 8 x 8 = 512 CTAs
    ck_main<<<grid, 128>>>(mu_p, lv_p, mu_g, lv_g);
    ck_reduce<<<NB, 512>>>(out);
}

// round 8
// speedup vs baseline: 1.0907x; 1.0170x over previous
#include <cuda_runtime.h>
#include <float.h>

// ChamferLossKL: bs=8, n=2048, d=4.
// t_ij = S_ij + csb_j + ca_i = 2*KL_ij + 4, computed ONCE per pair.
//   S = sum_d A_id*iv_jd + sum_d mu_id*w_jd
//   A = exp(la)+mu_a^2, ca = -sum(la); iv = exp(-lb), w = -2*mu_b*iv,
//   csb = sum(mu_b^2*iv) + sum(lb)
// loss_b = 0.5*(sum_i min_j t + sum_j min_i t) - 4*NP
// Thread: 4 i-chains x 2 packed j per iteration = 8 pair-values/lane/iter.
// Mins -> reversed-keyed uints -> global atomicMax (zero-init = identity),
// reduce kernel reads 16KB/batch, resets keys to zero for next replay.

#define NB 8
#define NP 2048
#define ITILE 512           // i per CTA (4 per thread)
#define NITILE 4
#define CHJ 256             // j per CTA
#define CHP 128             // j-pairs per CTA
#define NCH 8

typedef unsigned long long ull;

__device__ __forceinline__ ull ffma2(ull a, ull b, ull c) {
    ull d; asm("fma.rn.f32x2 %0, %1, %2, %3;" : "=l"(d) : "l"(a), "l"(b), "l"(c));
    return d;
}
__device__ __forceinline__ ull fadd2(ull a, ull b) {
    ull d; asm("add.rn.f32x2 %0, %1, %2;" : "=l"(d) : "l"(a), "l"(b));
    return d;
}
__device__ __forceinline__ ull packdup(float x) {
    ull d; asm("mov.b64 %0, {%1, %1};" : "=l"(d) : "f"(x));
    return d;
}
__device__ __forceinline__ void unpk(ull v, float& lo, float& hi) {
    asm("mov.b64 {%0, %1}, %2;" : "=f"(lo), "=f"(hi) : "l"(v));
}
__device__ __forceinline__ void lds_v2(ull& a, ull& b, unsigned int addr) {
    asm volatile("ld.shared.v2.u64 {%0, %1}, [%2];" : "=l"(a), "=l"(b) : "r"(addr));
}
__device__ __forceinline__ ull lds_1(unsigned int addr) {
    ull a; asm volatile("ld.shared.u64 %0, [%1];" : "=l"(a) : "r"(addr));
    return a;
}
// order-preserving float<->uint keys (exact, total order)
__device__ __forceinline__ unsigned int skey(float f) {
    unsigned int u = __float_as_uint(f);
    return u ^ ((unsigned int)((int)u >> 31) | 0x80000000u);
}
__device__ __forceinline__ float unkey(unsigned int u) {
    unsigned int b = u ^ ((unsigned int)((int)(~u) >> 31) | 0x80000000u);
    return __uint_as_float(b);
}
__device__ __forceinline__ unsigned int redux_umin(unsigned int v) {
    unsigned int r;
    asm("redux.sync.min.u32 %0, %1, 0xffffffff;" : "=r"(r) : "r"(v));
    return r;
}

// reversed-key min accumulators (zero = identity; reduce resets after use)
__device__ unsigned int g_rowk[NB * NP];   // 64 KB, static zero-init
__device__ unsigned int g_colk[NB * NP];   // 64 KB, static zero-init

// grid (NITILE, NB, NCH) = 256 CTAs, 128 threads.
__global__ __launch_bounds__(128) void ck_main(const float* __restrict__ mu_p,
                                               const float* __restrict__ lv_p,
                                               const float* __restrict__ mu_g,
                                               const float* __restrict__ lv_g) {
    __shared__ float4 s_stream[CHP * 5];  // 10 KB
    __shared__ uint2  s_col[4 * CHP];     // 4 KB (skey format)

    int tid  = threadIdx.x;
    int lane = tid & 31;
    int w    = tid >> 5;
    int b     = blockIdx.y;
    int itile = blockIdx.x;
    int ch    = blockIdx.z;

    // ---- self coefficients: four i per thread ----
    int i0 = itile * ITILE + tid;
    ull cfA[4][4], cfM[4][4], cfC[4];
#pragma unroll
    for (int c = 0; c < 4; c++) {
        int i = i0 + c * 128;
        float4 mp = reinterpret_cast<const float4*>(mu_p)[b * NP + i];
        float4 lp = reinterpret_cast<const float4*>(lv_p)[b * NP + i];
        cfA[c][0] = packdup(expf(lp.x) + mp.x * mp.x);
        cfA[c][1] = packdup(expf(lp.y) + mp.y * mp.y);
        cfA[c][2] = packdup(expf(lp.z) + mp.z * mp.z);
        cfA[c][3] = packdup(expf(lp.w) + mp.w * mp.w);
        cfM[c][0] = packdup(mp.x); cfM[c][1] = packdup(mp.y);
        cfM[c][2] = packdup(mp.z); cfM[c][3] = packdup(mp.w);
        cfC[c]    = packdup(-(lp.x + lp.y + lp.z + lp.w));
    }

    // ---- stream prep (gts): thread t builds j-pair t ----
    {
        int j0 = ch * CHJ + 2 * tid;
        float4 mg0 = reinterpret_cast<const float4*>(mu_g)[b * NP + j0];
        float4 lg0 = reinterpret_cast<const float4*>(lv_g)[b * NP + j0];
        float4 mg1 = reinterpret_cast<const float4*>(mu_g)[b * NP + j0 + 1];
        float4 lg1 = reinterpret_cast<const float4*>(lv_g)[b * NP + j0 + 1];
        float4 iv0, iv1, w0, w1;
        iv0.x = expf(-lg0.x); iv0.y = expf(-lg0.y); iv0.z = expf(-lg0.z); iv0.w = expf(-lg0.w);
        iv1.x = expf(-lg1.x); iv1.y = expf(-lg1.y); iv1.z = expf(-lg1.z); iv1.w = expf(-lg1.w);
        w0.x = -2.f * mg0.x * iv0.x; w0.y = -2.f * mg0.y * iv0.y;
        w0.z = -2.f * mg0.z * iv0.z; w0.w = -2.f * mg0.w * iv0.w;
        w1.x = -2.f * mg1.x * iv1.x; w1.y = -2.f * mg1.y * iv1.y;
        w1.z = -2.f * mg1.z * iv1.z; w1.w = -2.f * mg1.w * iv1.w;
        float csb0 = mg0.x * mg0.x * iv0.x + mg0.y * mg0.y * iv0.y
                   + mg0.z * mg0.z * iv0.z + mg0.w * mg0.w * iv0.w
                   + lg0.x + lg0.y + lg0.z + lg0.w;
        float csb1 = mg1.x * mg1.x * iv1.x + mg1.y * mg1.y * iv1.y
                   + mg1.z * mg1.z * iv1.z + mg1.w * mg1.w * iv1.w
                   + lg1.x + lg1.y + lg1.z + lg1.w;
        s_stream[tid * 5 + 0] = make_float4(iv0.x, iv1.x, iv0.y, iv1.y);
        s_stream[tid * 5 + 1] = make_float4(iv0.z, iv1.z, iv0.w, iv1.w);
        s_stream[tid * 5 + 2] = make_float4(w0.x, w1.x, w0.y, w1.y);
        s_stream[tid * 5 + 3] = make_float4(w0.z, w1.z, w0.w, w1.w);
        s_stream[tid * 5 + 4] = make_float4(csb0, csb1, 0.f, 0.f);
    }
    __syncthreads();

    unsigned int sbase = (unsigned int)__cvta_generic_to_shared(s_stream);
    float rmin[4][2];
#pragma unroll
    for (int c = 0; c < 4; c++) { rmin[c][0] = FLT_MAX; rmin[c][1] = FLT_MAX; }

    unsigned int ad = sbase;
#pragma unroll 2
    for (int p = 0; p < CHP; p++) {
        ull q0, q1, q2, q3, r0, r1, r2, r3;
        lds_v2(q0, q1, ad);
        lds_v2(q2, q3, ad + 16);
        lds_v2(r0, r1, ad + 32);
        lds_v2(r2, r3, ad + 48);
        ull csb = lds_1(ad + 64);

        float tl[4], th[4];
#pragma unroll
        for (int c = 0; c < 4; c++) {
            ull s = ffma2(cfA[c][0], q0, cfC[c]);
            s = ffma2(cfA[c][1], q1, s);
            s = ffma2(cfA[c][2], q2, s);
            s = ffma2(cfA[c][3], q3, s);
            s = ffma2(cfM[c][0], r0, s);
            s = ffma2(cfM[c][1], r1, s);
            s = ffma2(cfM[c][2], r2, s);
            s = ffma2(cfM[c][3], r3, s);
            ull t = fadd2(s, csb);
            unpk(t, tl[c], th[c]);
            rmin[c][0] = fminf(rmin[c][0], tl[c]);
            rmin[c][1] = fminf(rmin[c][1], th[c]);
        }
        float clo = fminf(fminf(tl[0], tl[1]), fminf(tl[2], tl[3]));
        float chi = fminf(fminf(th[0], th[1]), fminf(th[2], th[3]));
        unsigned int k0 = redux_umin(skey(clo));
        unsigned int k1 = redux_umin(skey(chi));
        if (lane == 0) s_col[w * CHP + p] = make_uint2(k0, k1);
        ad += 80;
    }

    // row mins -> keyed atomicMax (8 contenders per address)
#pragma unroll
    for (int c = 0; c < 4; c++) {
        float m = fminf(rmin[c][0], rmin[c][1]);
        atomicMax(&g_rowk[b * NP + i0 + c * 128], ~skey(m));
    }

    __syncthreads();
    {
        uint2 m0 = s_col[tid], m1 = s_col[CHP + tid];
        uint2 m2 = s_col[2 * CHP + tid], m3 = s_col[3 * CHP + tid];
        unsigned int kx = min(min(m0.x, m1.x), min(m2.x, m3.x));
        unsigned int ky = min(min(m0.y, m1.y), min(m2.y, m3.y));
        int j0 = ch * CHJ + 2 * tid;
        atomicMax(&g_colk[b * NP + j0],     ~kx);
        atomicMax(&g_colk[b * NP + j0 + 1], ~ky);
    }
}

// grid NB = 8 CTAs, 256 threads. Reads 16 KB/batch, resets keys to 0.
__global__ __launch_bounds__(256) void ck_reduce(float* __restrict__ out) {
    int b = blockIdx.x;
    int tid = threadIdx.x;
    float sum = 0.f;
#pragma unroll
    for (int k = 0; k < NP / 256; k++) {
        int idx = b * NP + k * 256 + tid;
        unsigned int rk = g_rowk[idx];
        unsigned int ck = g_colk[idx];
        sum += unkey(~rk) + unkey(~ck);
        g_rowk[idx] = 0u;   // reset for next graph replay
        g_colk[idx] = 0u;
    }
    __shared__ float red[256];
    red[tid] = sum;
    __syncthreads();
    for (int st = 128; st > 0; st >>= 1) {
        if (tid < st) red[tid] += red[tid + st];
        __syncthreads();
    }
    if (tid == 0) out[b] = 0.5f * red[0] - 2.0f * (2.0f * NP);
}

extern "C" void kernel_launch(void* const* d_in, const int* in_sizes, int n_in,
                              void* d_out, int out_size) {
    const float* mu_p = (const float*)d_in[0];
    const float* lv_p = (const float*)d_in[1];
    const float* mu_g = (const float*)d_in[2];
    const float* lv_g = (const float*)d_in[3];
    float* out = (float*)d_out;

    dim3 grid(NITILE, NB, NCH);  // 4 x 8 x 8 = 256 CTAs
    ck_main<<<grid, 128>>>(mu_p, lv_p, mu_g, lv_g);
    ck_reduce<<<NB, 256>>>(out);
}

// round 9
// speedup vs baseline: 1.1507x; 1.0550x over previous
#include <cuda_runtime.h>
#include <float.h>

// ChamferLossKL: bs=8, n=2048, d=4. Single fused kernel.
// t_ij = S_ij + csb_j + ca_i = 2*KL_ij + 4, computed ONCE per pair.
//   S = sum_d A_id*iv_jd + sum_d mu_id*w_jd
//   A = exp(la)+mu_a^2, ca = -sum(la); iv = exp(-lb), w = -2*mu_b*iv,
//   csb = sum(mu_b^2*iv) + sum(lb)
// loss_b = 0.5*(sum_i min_j t + sum_j min_i t) - 4*NP
// Thread: 4 i-chains x 2 packed j per iteration. Mins -> reversed-key
// atomicMax (zero = identity). Last CTA per batch reduces + resets state.

#define NB 8
#define NP 2048
#define ITILE 512           // i per CTA (4 per thread)
#define NITILE 4
#define CHJ 256             // j per CTA
#define CHP 128             // j-pairs per CTA
#define NCH 8
#define CTAS_PER_B (NITILE * NCH)   // 32

typedef unsigned long long ull;

__device__ __forceinline__ ull ffma2(ull a, ull b, ull c) {
    ull d; asm("fma.rn.f32x2 %0, %1, %2, %3;" : "=l"(d) : "l"(a), "l"(b), "l"(c));
    return d;
}
__device__ __forceinline__ ull fadd2(ull a, ull b) {
    ull d; asm("add.rn.f32x2 %0, %1, %2;" : "=l"(d) : "l"(a), "l"(b));
    return d;
}
__device__ __forceinline__ ull packdup(float x) {
    ull d; asm("mov.b64 %0, {%1, %1};" : "=l"(d) : "f"(x));
    return d;
}
__device__ __forceinline__ void unpk(ull v, float& lo, float& hi) {
    asm("mov.b64 {%0, %1}, %2;" : "=f"(lo), "=f"(hi) : "l"(v));
}
__device__ __forceinline__ void lds_v2(ull& a, ull& b, unsigned int addr) {
    asm volatile("ld.shared.v2.u64 {%0, %1}, [%2];" : "=l"(a), "=l"(b) : "r"(addr));
}
__device__ __forceinline__ ull lds_1(unsigned int addr) {
    ull a; asm volatile("ld.shared.u64 %0, [%1];" : "=l"(a) : "r"(addr));
    return a;
}
// order-preserving float<->uint keys (exact, total order)
__device__ __forceinline__ unsigned int skey(float f) {
    unsigned int u = __float_as_uint(f);
    return u ^ ((unsigned int)((int)u >> 31) | 0x80000000u);
}
__device__ __forceinline__ float unkey(unsigned int u) {
    unsigned int b = u ^ ((unsigned int)((int)(~u) >> 31) | 0x80000000u);
    return __uint_as_float(b);
}
__device__ __forceinline__ unsigned int redux_umin(unsigned int v) {
    unsigned int r;
    asm("redux.sync.min.u32 %0, %1, 0xffffffff;" : "=r"(r) : "r"(v));
    return r;
}

// reversed-key min accumulators (zero = identity; last CTA resets after use)
__device__ unsigned int g_rowk[NB * NP];   // 64 KB, static zero-init
__device__ unsigned int g_colk[NB * NP];   // 64 KB, static zero-init
__device__ unsigned int g_done[NB];        // arrival counters, zero-init

// grid (NITILE, NB, NCH) = 256 CTAs, 128 threads.
__global__ __launch_bounds__(128) void ck_main(const float* __restrict__ mu_p,
                                               const float* __restrict__ lv_p,
                                               const float* __restrict__ mu_g,
                                               const float* __restrict__ lv_g,
                                               float* __restrict__ out) {
    __shared__ float4 s_stream[CHP * 5];  // 10 KB
    __shared__ uint2  s_col[4 * CHP];     // 4 KB (skey format)
    __shared__ unsigned int s_last;

    int tid  = threadIdx.x;
    int lane = tid & 31;
    int w    = tid >> 5;
    int b     = blockIdx.y;
    int itile = blockIdx.x;
    int ch    = blockIdx.z;

    // ---- self coefficients: four i per thread ----
    int i0 = itile * ITILE + tid;
    ull cfA[4][4], cfM[4][4], cfC[4];
#pragma unroll
    for (int c = 0; c < 4; c++) {
        int i = i0 + c * 128;
        float4 mp = reinterpret_cast<const float4*>(mu_p)[b * NP + i];
        float4 lp = reinterpret_cast<const float4*>(lv_p)[b * NP + i];
        cfA[c][0] = packdup(expf(lp.x) + mp.x * mp.x);
        cfA[c][1] = packdup(expf(lp.y) + mp.y * mp.y);
        cfA[c][2] = packdup(expf(lp.z) + mp.z * mp.z);
        cfA[c][3] = packdup(expf(lp.w) + mp.w * mp.w);
        cfM[c][0] = packdup(mp.x); cfM[c][1] = packdup(mp.y);
        cfM[c][2] = packdup(mp.z); cfM[c][3] = packdup(mp.w);
        cfC[c]    = packdup(-(lp.x + lp.y + lp.z + lp.w));
    }

    // ---- stream prep (gts): thread t builds j-pair t ----
    {
        int j0 = ch * CHJ + 2 * tid;
        float4 mg0 = reinterpret_cast<const float4*>(mu_g)[b * NP + j0];
        float4 lg0 = reinterpret_cast<const float4*>(lv_g)[b * NP + j0];
        float4 mg1 = reinterpret_cast<const float4*>(mu_g)[b * NP + j0 + 1];
        float4 lg1 = reinterpret_cast<const float4*>(lv_g)[b * NP + j0 + 1];
        float4 iv0, iv1, w0, w1;
        iv0.x = expf(-lg0.x); iv0.y = expf(-lg0.y); iv0.z = expf(-lg0.z); iv0.w = expf(-lg0.w);
        iv1.x = expf(-lg1.x); iv1.y = expf(-lg1.y); iv1.z = expf(-lg1.z); iv1.w = expf(-lg1.w);
        w0.x = -2.f * mg0.x * iv0.x; w0.y = -2.f * mg0.y * iv0.y;
        w0.z = -2.f * mg0.z * iv0.z; w0.w = -2.f * mg0.w * iv0.w;
        w1.x = -2.f * mg1.x * iv1.x; w1.y = -2.f * mg1.y * iv1.y;
        w1.z = -2.f * mg1.z * iv1.z; w1.w = -2.f * mg1.w * iv1.w;
        float csb0 = mg0.x * mg0.x * iv0.x + mg0.y * mg0.y * iv0.y
                   + mg0.z * mg0.z * iv0.z + mg0.w * mg0.w * iv0.w
                   + lg0.x + lg0.y + lg0.z + lg0.w;
        float csb1 = mg1.x * mg1.x * iv1.x + mg1.y * mg1.y * iv1.y
                   + mg1.z * mg1.z * iv1.z + mg1.w * mg1.w * iv1.w
                   + lg1.x + lg1.y + lg1.z + lg1.w;
        s_stream[tid * 5 + 0] = make_float4(iv0.x, iv1.x, iv0.y, iv1.y);
        s_stream[tid * 5 + 1] = make_float4(iv0.z, iv1.z, iv0.w, iv1.w);
        s_stream[tid * 5 + 2] = make_float4(w0.x, w1.x, w0.y, w1.y);
        s_stream[tid * 5 + 3] = make_float4(w0.z, w1.z, w0.w, w1.w);
        s_stream[tid * 5 + 4] = make_float4(csb0, csb1, 0.f, 0.f);
    }
    __syncthreads();

    unsigned int sbase = (unsigned int)__cvta_generic_to_shared(s_stream);
    float rmin[4][2];
#pragma unroll
    for (int c = 0; c < 4; c++) { rmin[c][0] = FLT_MAX; rmin[c][1] = FLT_MAX; }

    unsigned int ad = sbase;
#pragma unroll 2
    for (int p = 0; p < CHP; p++) {
        ull q0, q1, q2, q3, r0, r1, r2, r3;
        lds_v2(q0, q1, ad);
        lds_v2(q2, q3, ad + 16);
        lds_v2(r0, r1, ad + 32);
        lds_v2(r2, r3, ad + 48);
        ull csb = lds_1(ad + 64);

        float tl[4], th[4];
#pragma unroll
        for (int c = 0; c < 4; c++) {
            ull s = ffma2(cfA[c][0], q0, cfC[c]);
            s = ffma2(cfA[c][1], q1, s);
            s = ffma2(cfA[c][2], q2, s);
            s = ffma2(cfA[c][3], q3, s);
            s = ffma2(cfM[c][0], r0, s);
            s = ffma2(cfM[c][1], r1, s);
            s = ffma2(cfM[c][2], r2, s);
            s = ffma2(cfM[c][3], r3, s);
            ull t = fadd2(s, csb);
            unpk(t, tl[c], th[c]);
            rmin[c][0] = fminf(rmin[c][0], tl[c]);
            rmin[c][1] = fminf(rmin[c][1], th[c]);
        }
        float clo = fminf(fminf(tl[0], tl[1]), fminf(tl[2], tl[3]));
        float chi = fminf(fminf(th[0], th[1]), fminf(th[2], th[3]));
        unsigned int k0 = redux_umin(skey(clo));
        unsigned int k1 = redux_umin(skey(chi));
        if (lane == 0) s_col[w * CHP + p] = make_uint2(k0, k1);
        ad += 80;
    }

    // row mins -> keyed atomicMax (8 contenders per address)
#pragma unroll
    for (int c = 0; c < 4; c++) {
        float m = fminf(rmin[c][0], rmin[c][1]);
        atomicMax(&g_rowk[b * NP + i0 + c * 128], ~skey(m));
    }

    __syncthreads();
    {
        uint2 m0 = s_col[tid], m1 = s_col[CHP + tid];
        uint2 m2 = s_col[2 * CHP + tid], m3 = s_col[3 * CHP + tid];
        unsigned int kx = min(min(m0.x, m1.x), min(m2.x, m3.x));
        unsigned int ky = min(min(m0.y, m1.y), min(m2.y, m3.y));
        int j0 = ch * CHJ + 2 * tid;
        atomicMax(&g_colk[b * NP + j0],     ~kx);
        atomicMax(&g_colk[b * NP + j0 + 1], ~ky);
    }

    // ---- fused tail: last CTA of this batch reduces + resets ----
    __threadfence();
    if (tid == 0) {
        unsigned int old = atomicAdd(&g_done[b], 1u);
        s_last = (old == CTAS_PER_B - 1) ? 1u : 0u;
    }
    __syncthreads();
    if (s_last) {
        __threadfence();  // acquire: all batch-b key writes visible
        float sum = 0.f;
#pragma unroll
        for (int k = 0; k < NP / 128; k++) {   // 16 iters, 128 thr
            int idx = b * NP + k * 128 + tid;
            unsigned int rk = g_rowk[idx];
            unsigned int ck = g_colk[idx];
            sum += unkey(~rk) + unkey(~ck);
            g_rowk[idx] = 0u;   // reset for next graph replay
            g_colk[idx] = 0u;
        }
        __shared__ float red[128];
        red[tid] = sum;
        __syncthreads();
        for (int st = 64; st > 0; st >>= 1) {
            if (tid < st) red[tid] += red[tid + st];
            __syncthreads();
        }
        if (tid == 0) {
            out[b] = 0.5f * red[0] - 2.0f * (2.0f * NP);
            g_done[b] = 0u;     // reset counter
        }
    }
}

extern "C" void kernel_launch(void* const* d_in, const int* in_sizes, int n_in,
                              void* d_out, int out_size) {
    const float* mu_p = (const float*)d_in[0];
    const float* lv_p = (const float*)d_in[1];
    const float* mu_g = (const float*)d_in[2];
    const float* lv_g = (const float*)d_in[3];
    float* out = (float*)d_out;

    dim3 grid(NITILE, NB, NCH);  // 4 x 8 x 8 = 256 CTAs
    ck_main<<<grid, 128>>>(mu_p, lv_p, mu_g, lv_g, out);
}

// round 10
// speedup vs baseline: 1.2477x; 1.0843x over previous
#include <cuda_runtime.h>
#include <float.h>

// ChamferLossKL: bs=8, n=2048, d=4. Single fused kernel.
// t_ij = S_ij + csb_j + ca_i = 2*KL_ij + 4, computed ONCE per pair.
//   S = sum_d A_id*iv_jd + sum_d mu_id*w_jd
//   A = exp(la)+mu_a^2, ca = -sum(la); iv = exp(-lb), w = -2*mu_b*iv,
//   csb = sum(mu_b^2*iv) + sum(lb)
// loss_b = 0.5*(sum_i min_j t + sum_j min_i t) - 4*NP
// Thread: 4 i-chains x 2 packed j per iteration. Mins -> reversed-key
// atomicMax (zero = identity). Last CTA per batch reduces + resets state.
// R10: 512 CTAs (j split 16 ways) for 2x occupancy / latency hiding.

#define NB 8
#define NP 2048
#define ITILE 512           // i per CTA (4 per thread)
#define NITILE 4
#define CHJ 128             // j per CTA
#define CHP 64              // j-pairs per CTA
#define NCH 16
#define CTAS_PER_B (NITILE * NCH)   // 64

typedef unsigned long long ull;

__device__ __forceinline__ ull ffma2(ull a, ull b, ull c) {
    ull d; asm("fma.rn.f32x2 %0, %1, %2, %3;" : "=l"(d) : "l"(a), "l"(b), "l"(c));
    return d;
}
__device__ __forceinline__ ull fadd2(ull a, ull b) {
    ull d; asm("add.rn.f32x2 %0, %1, %2;" : "=l"(d) : "l"(a), "l"(b));
    return d;
}
__device__ __forceinline__ ull packdup(float x) {
    ull d; asm("mov.b64 %0, {%1, %1};" : "=l"(d) : "f"(x));
    return d;
}
__device__ __forceinline__ void unpk(ull v, float& lo, float& hi) {
    asm("mov.b64 {%0, %1}, %2;" : "=f"(lo), "=f"(hi) : "l"(v));
}
__device__ __forceinline__ void lds_v2(ull& a, ull& b, unsigned int addr) {
    asm volatile("ld.shared.v2.u64 {%0, %1}, [%2];" : "=l"(a), "=l"(b) : "r"(addr));
}
__device__ __forceinline__ ull lds_1(unsigned int addr) {
    ull a; asm volatile("ld.shared.u64 %0, [%1];" : "=l"(a) : "r"(addr));
    return a;
}
// order-preserving float<->uint keys (exact, total order)
__device__ __forceinline__ unsigned int skey(float f) {
    unsigned int u = __float_as_uint(f);
    return u ^ ((unsigned int)((int)u >> 31) | 0x80000000u);
}
__device__ __forceinline__ float unkey(unsigned int u) {
    unsigned int b = u ^ ((unsigned int)((int)(~u) >> 31) | 0x80000000u);
    return __uint_as_float(b);
}
__device__ __forceinline__ unsigned int redux_umin(unsigned int v) {
    unsigned int r;
    asm("redux.sync.min.u32 %0, %1, 0xffffffff;" : "=r"(r) : "r"(v));
    return r;
}

// reversed-key min accumulators (zero = identity; last CTA resets after use)
__device__ unsigned int g_rowk[NB * NP];   // 64 KB, static zero-init
__device__ unsigned int g_colk[NB * NP];   // 64 KB, static zero-init
__device__ unsigned int g_done[NB];        // arrival counters, zero-init

// grid (NITILE, NB, NCH) = 512 CTAs, 128 threads.
__global__ __launch_bounds__(128) void ck_main(const float* __restrict__ mu_p,
                                               const float* __restrict__ lv_p,
                                               const float* __restrict__ mu_g,
                                               const float* __restrict__ lv_g,
                                               float* __restrict__ out) {
    __shared__ float4 s_stream[CHP * 5];  // 5 KB
    __shared__ uint2  s_col[4 * CHP];     // 2 KB (skey format)
    __shared__ unsigned int s_last;

    int tid  = threadIdx.x;
    int lane = tid & 31;
    int w    = tid >> 5;
    int b     = blockIdx.y;
    int itile = blockIdx.x;
    int ch    = blockIdx.z;

    // ---- self coefficients: four i per thread ----
    int i0 = itile * ITILE + tid;
    ull cfA[4][4], cfM[4][4], cfC[4];
#pragma unroll
    for (int c = 0; c < 4; c++) {
        int i = i0 + c * 128;
        float4 mp = reinterpret_cast<const float4*>(mu_p)[b * NP + i];
        float4 lp = reinterpret_cast<const float4*>(lv_p)[b * NP + i];
        cfA[c][0] = packdup(expf(lp.x) + mp.x * mp.x);
        cfA[c][1] = packdup(expf(lp.y) + mp.y * mp.y);
        cfA[c][2] = packdup(expf(lp.z) + mp.z * mp.z);
        cfA[c][3] = packdup(expf(lp.w) + mp.w * mp.w);
        cfM[c][0] = packdup(mp.x); cfM[c][1] = packdup(mp.y);
        cfM[c][2] = packdup(mp.z); cfM[c][3] = packdup(mp.w);
        cfC[c]    = packdup(-(lp.x + lp.y + lp.z + lp.w));
    }

    // ---- stream prep (gts): threads 0..63 build one j-pair each ----
    if (tid < CHP) {
        int j0 = ch * CHJ + 2 * tid;
        float4 mg0 = reinterpret_cast<const float4*>(mu_g)[b * NP + j0];
        float4 lg0 = reinterpret_cast<const float4*>(lv_g)[b * NP + j0];
        float4 mg1 = reinterpret_cast<const float4*>(mu_g)[b * NP + j0 + 1];
        float4 lg1 = reinterpret_cast<const float4*>(lv_g)[b * NP + j0 + 1];
        float4 iv0, iv1, w0, w1;
        iv0.x = expf(-lg0.x); iv0.y = expf(-lg0.y); iv0.z = expf(-lg0.z); iv0.w = expf(-lg0.w);
        iv1.x = expf(-lg1.x); iv1.y = expf(-lg1.y); iv1.z = expf(-lg1.z); iv1.w = expf(-lg1.w);
        w0.x = -2.f * mg0.x * iv0.x; w0.y = -2.f * mg0.y * iv0.y;
        w0.z = -2.f * mg0.z * iv0.z; w0.w = -2.f * mg0.w * iv0.w;
        w1.x = -2.f * mg1.x * iv1.x; w1.y = -2.f * mg1.y * iv1.y;
        w1.z = -2.f * mg1.z * iv1.z; w1.w = -2.f * mg1.w * iv1.w;
        float csb0 = mg0.x * mg0.x * iv0.x + mg0.y * mg0.y * iv0.y
                   + mg0.z * mg0.z * iv0.z + mg0.w * mg0.w * iv0.w
                   + lg0.x + lg0.y + lg0.z + lg0.w;
        float csb1 = mg1.x * mg1.x * iv1.x + mg1.y * mg1.y * iv1.y
                   + mg1.z * mg1.z * iv1.z + mg1.w * mg1.w * iv1.w
                   + lg1.x + lg1.y + lg1.z + lg1.w;
        s_stream[tid * 5 + 0] = make_float4(iv0.x, iv1.x, iv0.y, iv1.y);
        s_stream[tid * 5 + 1] = make_float4(iv0.z, iv1.z, iv0.w, iv1.w);
        s_stream[tid * 5 + 2] = make_float4(w0.x, w1.x, w0.y, w1.y);
        s_stream[tid * 5 + 3] = make_float4(w0.z, w1.z, w0.w, w1.w);
        s_stream[tid * 5 + 4] = make_float4(csb0, csb1, 0.f, 0.f);
    }
    __syncthreads();

    unsigned int sbase = (unsigned int)__cvta_generic_to_shared(s_stream);
    float rmin[4][2];
#pragma unroll
    for (int c = 0; c < 4; c++) { rmin[c][0] = FLT_MAX; rmin[c][1] = FLT_MAX; }

    unsigned int ad = sbase;
#pragma unroll 2
    for (int p = 0; p < CHP; p++) {
        ull q0, q1, q2, q3, r0, r1, r2, r3;
        lds_v2(q0, q1, ad);
        lds_v2(q2, q3, ad + 16);
        lds_v2(r0, r1, ad + 32);
        lds_v2(r2, r3, ad + 48);
        ull csb = lds_1(ad + 64);

        float tl[4], th[4];
#pragma unroll
        for (int c = 0; c < 4; c++) {
            ull s = ffma2(cfA[c][0], q0, cfC[c]);
            s = ffma2(cfA[c][1], q1, s);
            s = ffma2(cfA[c][2], q2, s);
            s = ffma2(cfA[c][3], q3, s);
            s = ffma2(cfM[c][0], r0, s);
            s = ffma2(cfM[c][1], r1, s);
            s = ffma2(cfM[c][2], r2, s);
            s = ffma2(cfM[c][3], r3, s);
            ull t = fadd2(s, csb);
            unpk(t, tl[c], th[c]);
            rmin[c][0] = fminf(rmin[c][0], tl[c]);
            rmin[c][1] = fminf(rmin[c][1], th[c]);
        }
        float clo = fminf(fminf(tl[0], tl[1]), fminf(tl[2], tl[3]));
        float chi = fminf(fminf(th[0], th[1]), fminf(th[2], th[3]));
        unsigned int k0 = redux_umin(skey(clo));
        unsigned int k1 = redux_umin(skey(chi));
        if (lane == 0) s_col[w * CHP + p] = make_uint2(k0, k1);
        ad += 80;
    }

    // row mins -> keyed atomicMax (16 contenders per address)
#pragma unroll
    for (int c = 0; c < 4; c++) {
        float m = fminf(rmin[c][0], rmin[c][1]);
        atomicMax(&g_rowk[b * NP + i0 + c * 128], ~skey(m));
    }

    __syncthreads();
    if (tid < CHP) {
        uint2 m0 = s_col[tid], m1 = s_col[CHP + tid];
        uint2 m2 = s_col[2 * CHP + tid], m3 = s_col[3 * CHP + tid];
        unsigned int kx = min(min(m0.x, m1.x), min(m2.x, m3.x));
        unsigned int ky = min(min(m0.y, m1.y), min(m2.y, m3.y));
        int j0 = ch * CHJ + 2 * tid;
        atomicMax(&g_colk[b * NP + j0],     ~kx);
        atomicMax(&g_colk[b * NP + j0 + 1], ~ky);
    }

    // ---- fused tail: last CTA of this batch reduces + resets ----
    __threadfence();
    if (tid == 0) {
        unsigned int old = atomicAdd(&g_done[b], 1u);
        s_last = (old == CTAS_PER_B - 1) ? 1u : 0u;
    }
    __syncthreads();
    if (s_last) {
        __threadfence();  // acquire: all batch-b key writes visible
        float sum = 0.f;
#pragma unroll
        for (int k = 0; k < NP / 128; k++) {   // 16 iters, 128 thr
            int idx = b * NP + k * 128 + tid;
            unsigned int rk = g_rowk[idx];
            unsigned int ck = g_colk[idx];
            sum += unkey(~rk) + unkey(~ck);
            g_rowk[idx] = 0u;   // reset for next graph replay
            g_colk[idx] = 0u;
        }
        __shared__ float red[128];
        red[tid] = sum;
        __syncthreads();
        for (int st = 64; st > 0; st >>= 1) {
            if (tid < st) red[tid] += red[tid + st];
            __syncthreads();
        }
        if (tid == 0) {
            out[b] = 0.5f * red[0] - 2.0f * (2.0f * NP);
            g_done[b] = 0u;     // reset counter
        }
    }
}

extern "C" void kernel_launch(void* const* d_in, const int* in_sizes, int n_in,
                              void* d_out, int out_size) {
    const float* mu_p = (const float*)d_in[0];
    const float* lv_p = (const float*)d_in[1];
    const float* mu_g = (const float*)d_in[2];
    const float* lv_g = (const float*)d_in[3];
    float* out = (float*)d_out;

    dim3 grid(NITILE, NB, NCH);  // 4 x 8 x 16 = 512 CTAs
    ck_main<<<grid, 128>>>(mu_p, lv_p, mu_g, lv_g, out);
}

// round 11
// speedup vs baseline: 1.3588x; 1.0890x over previous
#include <cuda_runtime.h>
#include <float.h>

// ChamferLossKL: bs=8, n=2048, d=4. Single fused kernel.
// t_ij = S_ij + csb_j + ca_i = 2*KL_ij + 4, computed ONCE per pair.
//   S = sum_d A_id*iv_jd + sum_d mu_id*w_jd
//   A = exp(la)+mu_a^2, ca = -sum(la); iv = exp(-lb), w = -2*mu_b*iv,
//   csb = sum(mu_b^2*iv) + sum(lb)
// loss_b = 0.5*(sum_i min_j t + sum_j min_i t) - 4*NP
// Thread: 4 i-chains x 2 packed j per iteration. Mins -> reversed-key
// atomicMax (zero = identity). Last CTA per batch reduces + resets state.
// R11: 1024 CTAs (j split 32 ways) -> ~7 warps/SMSP for latency hiding.

#define NB 8
#define NP 2048
#define ITILE 512           // i per CTA (4 per thread)
#define NITILE 4
#define CHJ 64              // j per CTA
#define CHP 32              // j-pairs per CTA
#define NCH 32
#define CTAS_PER_B (NITILE * NCH)   // 128

typedef unsigned long long ull;

__device__ __forceinline__ ull ffma2(ull a, ull b, ull c) {
    ull d; asm("fma.rn.f32x2 %0, %1, %2, %3;" : "=l"(d) : "l"(a), "l"(b), "l"(c));
    return d;
}
__device__ __forceinline__ ull fadd2(ull a, ull b) {
    ull d; asm("add.rn.f32x2 %0, %1, %2;" : "=l"(d) : "l"(a), "l"(b));
    return d;
}
__device__ __forceinline__ ull packdup(float x) {
    ull d; asm("mov.b64 %0, {%1, %1};" : "=l"(d) : "f"(x));
    return d;
}
__device__ __forceinline__ void unpk(ull v, float& lo, float& hi) {
    asm("mov.b64 {%0, %1}, %2;" : "=f"(lo), "=f"(hi) : "l"(v));
}
__device__ __forceinline__ void lds_v2(ull& a, ull& b, unsigned int addr) {
    asm volatile("ld.shared.v2.u64 {%0, %1}, [%2];" : "=l"(a), "=l"(b) : "r"(addr));
}
__device__ __forceinline__ ull lds_1(unsigned int addr) {
    ull a; asm volatile("ld.shared.u64 %0, [%1];" : "=l"(a) : "r"(addr));
    return a;
}
// order-preserving float<->uint keys (exact, total order)
__device__ __forceinline__ unsigned int skey(float f) {
    unsigned int u = __float_as_uint(f);
    return u ^ ((unsigned int)((int)u >> 31) | 0x80000000u);
}
__device__ __forceinline__ float unkey(unsigned int u) {
    unsigned int b = u ^ ((unsigned int)((int)(~u) >> 31) | 0x80000000u);
    return __uint_as_float(b);
}
__device__ __forceinline__ unsigned int redux_umin(unsigned int v) {
    unsigned int r;
    asm("redux.sync.min.u32 %0, %1, 0xffffffff;" : "=r"(r) : "r"(v));
    return r;
}

// reversed-key min accumulators (zero = identity; last CTA resets after use)
__device__ unsigned int g_rowk[NB * NP];   // 64 KB, static zero-init
__device__ unsigned int g_colk[NB * NP];   // 64 KB, static zero-init
__device__ unsigned int g_done[NB];        // arrival counters, zero-init

// grid (NITILE, NB, NCH) = 1024 CTAs, 128 threads.
__global__ __launch_bounds__(128) void ck_main(const float* __restrict__ mu_p,
                                               const float* __restrict__ lv_p,
                                               const float* __restrict__ mu_g,
                                               const float* __restrict__ lv_g,
                                               float* __restrict__ out) {
    __shared__ float4 s_stream[CHP * 5];  // 2.5 KB
    __shared__ uint2  s_col[4 * CHP];     // 1 KB (skey format)
    __shared__ unsigned int s_last;

    int tid  = threadIdx.x;
    int lane = tid & 31;
    int w    = tid >> 5;
    int b     = blockIdx.y;
    int itile = blockIdx.x;
    int ch    = blockIdx.z;

    // ---- self coefficients: four i per thread ----
    int i0 = itile * ITILE + tid;
    ull cfA[4][4], cfM[4][4], cfC[4];
#pragma unroll
    for (int c = 0; c < 4; c++) {
        int i = i0 + c * 128;
        float4 mp = reinterpret_cast<const float4*>(mu_p)[b * NP + i];
        float4 lp = reinterpret_cast<const float4*>(lv_p)[b * NP + i];
        cfA[c][0] = packdup(expf(lp.x) + mp.x * mp.x);
        cfA[c][1] = packdup(expf(lp.y) + mp.y * mp.y);
        cfA[c][2] = packdup(expf(lp.z) + mp.z * mp.z);
        cfA[c][3] = packdup(expf(lp.w) + mp.w * mp.w);
        cfM[c][0] = packdup(mp.x); cfM[c][1] = packdup(mp.y);
        cfM[c][2] = packdup(mp.z); cfM[c][3] = packdup(mp.w);
        cfC[c]    = packdup(-(lp.x + lp.y + lp.z + lp.w));
    }

    // ---- stream prep (gts): threads 0..31 build one j-pair each ----
    if (tid < CHP) {
        int j0 = ch * CHJ + 2 * tid;
        float4 mg0 = reinterpret_cast<const float4*>(mu_g)[b * NP + j0];
        float4 lg0 = reinterpret_cast<const float4*>(lv_g)[b * NP + j0];
        float4 mg1 = reinterpret_cast<const float4*>(mu_g)[b * NP + j0 + 1];
        float4 lg1 = reinterpret_cast<const float4*>(lv_g)[b * NP + j0 + 1];
        float4 iv0, iv1, w0, w1;
        iv0.x = expf(-lg0.x); iv0.y = expf(-lg0.y); iv0.z = expf(-lg0.z); iv0.w = expf(-lg0.w);
        iv1.x = expf(-lg1.x); iv1.y = expf(-lg1.y); iv1.z = expf(-lg1.z); iv1.w = expf(-lg1.w);
        w0.x = -2.f * mg0.x * iv0.x; w0.y = -2.f * mg0.y * iv0.y;
        w0.z = -2.f * mg0.z * iv0.z; w0.w = -2.f * mg0.w * iv0.w;
        w1.x = -2.f * mg1.x * iv1.x; w1.y = -2.f * mg1.y * iv1.y;
        w1.z = -2.f * mg1.z * iv1.z; w1.w = -2.f * mg1.w * iv1.w;
        float csb0 = mg0.x * mg0.x * iv0.x + mg0.y * mg0.y * iv0.y
                   + mg0.z * mg0.z * iv0.z + mg0.w * mg0.w * iv0.w
                   + lg0.x + lg0.y + lg0.z + lg0.w;
        float csb1 = mg1.x * mg1.x * iv1.x + mg1.y * mg1.y * iv1.y
                   + mg1.z * mg1.z * iv1.z + mg1.w * mg1.w * iv1.w
                   + lg1.x + lg1.y + lg1.z + lg1.w;
        s_stream[tid * 5 + 0] = make_float4(iv0.x, iv1.x, iv0.y, iv1.y);
        s_stream[tid * 5 + 1] = make_float4(iv0.z, iv1.z, iv0.w, iv1.w);
        s_stream[tid * 5 + 2] = make_float4(w0.x, w1.x, w0.y, w1.y);
        s_stream[tid * 5 + 3] = make_float4(w0.z, w1.z, w0.w, w1.w);
        s_stream[tid * 5 + 4] = make_float4(csb0, csb1, 0.f, 0.f);
    }
    __syncthreads();

    unsigned int sbase = (unsigned int)__cvta_generic_to_shared(s_stream);
    float rmin[4][2];
#pragma unroll
    for (int c = 0; c < 4; c++) { rmin[c][0] = FLT_MAX; rmin[c][1] = FLT_MAX; }

    unsigned int ad = sbase;
#pragma unroll 2
    for (int p = 0; p < CHP; p++) {
        ull q0, q1, q2, q3, r0, r1, r2, r3;
        lds_v2(q0, q1, ad);
        lds_v2(q2, q3, ad + 16);
        lds_v2(r0, r1, ad + 32);
        lds_v2(r2, r3, ad + 48);
        ull csb = lds_1(ad + 64);

        float tl[4], th[4];
#pragma unroll
        for (int c = 0; c < 4; c++) {
            ull s = ffma2(cfA[c][0], q0, cfC[c]);
            s = ffma2(cfA[c][1], q1, s);
            s = ffma2(cfA[c][2], q2, s);
            s = ffma2(cfA[c][3], q3, s);
            s = ffma2(cfM[c][0], r0, s);
            s = ffma2(cfM[c][1], r1, s);
            s = ffma2(cfM[c][2], r2, s);
            s = ffma2(cfM[c][3], r3, s);
            ull t = fadd2(s, csb);
            unpk(t, tl[c], th[c]);
            rmin[c][0] = fminf(rmin[c][0], tl[c]);
            rmin[c][1] = fminf(rmin[c][1], th[c]);
        }
        float clo = fminf(fminf(tl[0], tl[1]), fminf(tl[2], tl[3]));
        float chi = fminf(fminf(th[0], th[1]), fminf(th[2], th[3]));
        unsigned int k0 = redux_umin(skey(clo));
        unsigned int k1 = redux_umin(skey(chi));
        if (lane == 0) s_col[w * CHP + p] = make_uint2(k0, k1);
        ad += 80;
    }

    // row mins -> keyed atomicMax (32 contenders per address)
#pragma unroll
    for (int c = 0; c < 4; c++) {
        float m = fminf(rmin[c][0], rmin[c][1]);
        atomicMax(&g_rowk[b * NP + i0 + c * 128], ~skey(m));
    }

    __syncthreads();
    if (tid < CHP) {
        uint2 m0 = s_col[tid], m1 = s_col[CHP + tid];
        uint2 m2 = s_col[2 * CHP + tid], m3 = s_col[3 * CHP + tid];
        unsigned int kx = min(min(m0.x, m1.x), min(m2.x, m3.x));
        unsigned int ky = min(min(m0.y, m1.y), min(m2.y, m3.y));
        int j0 = ch * CHJ + 2 * tid;
        atomicMax(&g_colk[b * NP + j0],     ~kx);
        atomicMax(&g_colk[b * NP + j0 + 1], ~ky);
    }

    // ---- fused tail: last CTA of this batch reduces + resets ----
    __threadfence();
    if (tid == 0) {
        unsigned int old = atomicAdd(&g_done[b], 1u);
        s_last = (old == CTAS_PER_B - 1) ? 1u : 0u;
    }
    __syncthreads();
    if (s_last) {
        __threadfence();  // acquire: all batch-b key writes visible
        float sum = 0.f;
#pragma unroll
        for (int k = 0; k < NP / 128; k++) {   // 16 iters, 128 thr
            int idx = b * NP + k * 128 + tid;
            unsigned int rk = g_rowk[idx];
            unsigned int ck = g_colk[idx];
            sum += unkey(~rk) + unkey(~ck);
            g_rowk[idx] = 0u;   // reset for next graph replay
            g_colk[idx] = 0u;
        }
        __shared__ float red[128];
        red[tid] = sum;
        __syncthreads();
        for (int st = 64; st > 0; st >>= 1) {
            if (tid < st) red[tid] += red[tid + st];
            __syncthreads();
        }
        if (tid == 0) {
            out[b] = 0.5f * red[0] - 2.0f * (2.0f * NP);
            g_done[b] = 0u;     // reset counter
        }
    }
}

extern "C" void kernel_launch(void* const* d_in, const int* in_sizes, int n_in,
                              void* d_out, int out_size) {
    const float* mu_p = (const float*)d_in[0];
    const float* lv_p = (const float*)d_in[1];
    const float* mu_g = (const float*)d_in[2];
    const float* lv_g = (const float*)d_in[3];
    float* out = (float*)d_out;

    dim3 grid(NITILE, NB, NCH);  // 4 x 8 x 32 = 1024 CTAs
    ck_main<<<grid, 128>>>(mu_p, lv_p, mu_g, lv_g, out);
}

// round 13
// speedup vs baseline: 1.3645x; 1.0043x over previous
#include <cuda_runtime.h>
#include <float.h>

// ChamferLossKL: bs=8, n=2048, d=4. Single fused kernel.
// t_ij = S_ij + csb_j + ca_i = 2*KL_ij + 4  (> 0 since KL >= 0), once per pair.
//   S = sum_d A_id*iv_jd + sum_d mu_id*w_jd
//   A = exp(la)+mu_a^2, ca = -sum(la); iv = exp(-lb), w = -2*mu_b*iv,
//   csb = sum(mu_b^2*iv) + sum(lb)
// loss_b = 0.5*(sum_i min_j t + sum_j min_i t) - 4*NP
// Positivity => raw float bits are order-isomorphic to values: redux.min.u32
// and atomicMax(~bits) (zero identity) work on raw bits, no key transform.

#define NB 8
#define NP 2048
#define ITILE 512           // i per CTA (4 per thread)
#define NITILE 4
#define CHJ 64              // j per CTA
#define CHP 32              // j-pairs per CTA
#define NCH 32
#define CTAS_PER_B (NITILE * NCH)   // 128

typedef unsigned long long ull;

__device__ __forceinline__ ull ffma2(ull a, ull b, ull c) {
    ull d; asm("fma.rn.f32x2 %0, %1, %2, %3;" : "=l"(d) : "l"(a), "l"(b), "l"(c));
    return d;
}
__device__ __forceinline__ ull fadd2(ull a, ull b) {
    ull d; asm("add.rn.f32x2 %0, %1, %2;" : "=l"(d) : "l"(a), "l"(b));
    return d;
}
__device__ __forceinline__ ull packdup(float x) {
    ull d; asm("mov.b64 %0, {%1, %1};" : "=l"(d) : "f"(x));
    return d;
}
__device__ __forceinline__ void unpk(ull v, float& lo, float& hi) {
    asm("mov.b64 {%0, %1}, %2;" : "=f"(lo), "=f"(hi) : "l"(v));
}
__device__ __forceinline__ void lds_v2(ull& a, ull& b, unsigned int addr) {
    asm volatile("ld.shared.v2.u64 {%0, %1}, [%2];" : "=l"(a), "=l"(b) : "r"(addr));
}
__device__ __forceinline__ ull lds_1(unsigned int addr) {
    ull a; asm volatile("ld.shared.u64 %0, [%1];" : "=l"(a) : "r"(addr));
    return a;
}
__device__ __forceinline__ unsigned int redux_umin(unsigned int v) {
    unsigned int r;
    asm("redux.sync.min.u32 %0, %1, 0xffffffff;" : "=r"(r) : "r"(v));
    return r;
}

// ~rawbits min accumulators for positive floats (zero = identity)
__device__ unsigned int g_rowk[NB * NP];   // 64 KB, static zero-init
__device__ unsigned int g_colk[NB * NP];   // 64 KB, static zero-init
__device__ unsigned int g_done[NB];        // arrival counters, zero-init

// grid (NITILE, NB, NCH) = 1024 CTAs, 128 threads.
__global__ __launch_bounds__(128, 6) void ck_main(const float* __restrict__ mu_p,
                                                  const float* __restrict__ lv_p,
                                                  const float* __restrict__ mu_g,
                                                  const float* __restrict__ lv_g,
                                                  float* __restrict__ out) {
    __shared__ float4 s_stream[CHP * 5];  // 2.5 KB
    __shared__ uint2  s_col[4 * CHP];     // 1 KB (raw-bit mins)
    __shared__ unsigned int s_last;

    int tid  = threadIdx.x;
    int lane = tid & 31;
    int w    = tid >> 5;
    int b     = blockIdx.y;
    int itile = blockIdx.x;
    int ch    = blockIdx.z;

    // ---- self coefficients: four i per thread ----
    int i0 = itile * ITILE + tid;
    ull cfA[4][4], cfM[4][4], cfC[4];
#pragma unroll
    for (int c = 0; c < 4; c++) {
        int i = i0 + c * 128;
        float4 mp = reinterpret_cast<const float4*>(mu_p)[b * NP + i];
        float4 lp = reinterpret_cast<const float4*>(lv_p)[b * NP + i];
        cfA[c][0] = packdup(__expf(lp.x) + mp.x * mp.x);
        cfA[c][1] = packdup(__expf(lp.y) + mp.y * mp.y);
        cfA[c][2] = packdup(__expf(lp.z) + mp.z * mp.z);
        cfA[c][3] = packdup(__expf(lp.w) + mp.w * mp.w);
        cfM[c][0] = packdup(mp.x); cfM[c][1] = packdup(mp.y);
        cfM[c][2] = packdup(mp.z); cfM[c][3] = packdup(mp.w);
        cfC[c]    = packdup(-(lp.x + lp.y + lp.z + lp.w));
    }

    // ---- stream prep (gts): threads 0..31 build one j-pair each ----
    if (tid < CHP) {
        int j0 = ch * CHJ + 2 * tid;
        float4 mg0 = reinterpret_cast<const float4*>(mu_g)[b * NP + j0];
        float4 lg0 = reinterpret_cast<const float4*>(lv_g)[b * NP + j0];
        float4 mg1 = reinterpret_cast<const float4*>(mu_g)[b * NP + j0 + 1];
        float4 lg1 = reinterpret_cast<const float4*>(lv_g)[b * NP + j0 + 1];
        float4 iv0, iv1, w0, w1;
        iv0.x = __expf(-lg0.x); iv0.y = __expf(-lg0.y);
        iv0.z = __expf(-lg0.z); iv0.w = __expf(-lg0.w);
        iv1.x = __expf(-lg1.x); iv1.y = __expf(-lg1.y);
        iv1.z = __expf(-lg1.z); iv1.w = __expf(-lg1.w);
        w0.x = -2.f * mg0.x * iv0.x; w0.y = -2.f * mg0.y * iv0.y;
        w0.z = -2.f * mg0.z * iv0.z; w0.w = -2.f * mg0.w * iv0.w;
        w1.x = -2.f * mg1.x * iv1.x; w1.y = -2.f * mg1.y * iv1.y;
        w1.z = -2.f * mg1.z * iv1.z; w1.w = -2.f * mg1.w * iv1.w;
        float csb0 = mg0.x * mg0.x * iv0.x + mg0.y * mg0.y * iv0.y
                   + mg0.z * mg0.z * iv0.z + mg0.w * mg0.w * iv0.w
                   + lg0.x + lg0.y + lg0.z + lg0.w;
        float csb1 = mg1.x * mg1.x * iv1.x + mg1.y * mg1.y * iv1.y
                   + mg1.z * mg1.z * iv1.z + mg1.w * mg1.w * iv1.w
                   + lg1.x + lg1.y + lg1.z + lg1.w;
        s_stream[tid * 5 + 0] = make_float4(iv0.x, iv1.x, iv0.y, iv1.y);
        s_stream[tid * 5 + 1] = make_float4(iv0.z, iv1.z, iv0.w, iv1.w);
        s_stream[tid * 5 + 2] = make_float4(w0.x, w1.x, w0.y, w1.y);
        s_stream[tid * 5 + 3] = make_float4(w0.z, w1.z, w0.w, w1.w);
        s_stream[tid * 5 + 4] = make_float4(csb0, csb1, 0.f, 0.f);
    }
    __syncthreads();

    unsigned int sbase = (unsigned int)__cvta_generic_to_shared(s_stream);
    float rmin[4][2];
#pragma unroll
    for (int c = 0; c < 4; c++) { rmin[c][0] = FLT_MAX; rmin[c][1] = FLT_MAX; }

    unsigned int ad = sbase;
#pragma unroll 4
    for (int p = 0; p < CHP; p++) {
        ull q0, q1, q2, q3, r0, r1, r2, r3;
        lds_v2(q0, q1, ad);
        lds_v2(q2, q3, ad + 16);
        lds_v2(r0, r1, ad + 32);
        lds_v2(r2, r3, ad + 48);
        ull csb = lds_1(ad + 64);

        float tl[4], th[4];
#pragma unroll
        for (int c = 0; c < 4; c++) {
            ull s = ffma2(cfA[c][0], q0, cfC[c]);
            s = ffma2(cfA[c][1], q1, s);
            s = ffma2(cfA[c][2], q2, s);
            s = ffma2(cfA[c][3], q3, s);
            s = ffma2(cfM[c][0], r0, s);
            s = ffma2(cfM[c][1], r1, s);
            s = ffma2(cfM[c][2], r2, s);
            s = ffma2(cfM[c][3], r3, s);
            ull t = fadd2(s, csb);
            unpk(t, tl[c], th[c]);
            rmin[c][0] = fminf(rmin[c][0], tl[c]);
            rmin[c][1] = fminf(rmin[c][1], th[c]);
        }
        float clo = fminf(fminf(tl[0], tl[1]), fminf(tl[2], tl[3]));
        float chi = fminf(fminf(th[0], th[1]), fminf(th[2], th[3]));
        unsigned int k0 = redux_umin(__float_as_uint(clo));
        unsigned int k1 = redux_umin(__float_as_uint(chi));
        if (lane == 0) s_col[w * CHP + p] = make_uint2(k0, k1);
        ad += 80;
    }

    // row mins -> ~rawbits atomicMax (32 contenders per address)
#pragma unroll
    for (int c = 0; c < 4; c++) {
        float m = fminf(rmin[c][0], rmin[c][1]);
        atomicMax(&g_rowk[b * NP + i0 + c * 128], ~__float_as_uint(m));
    }

    __syncthreads();
    if (tid < CHP) {
        uint2 m0 = s_col[tid], m1 = s_col[CHP + tid];
        uint2 m2 = s_col[2 * CHP + tid], m3 = s_col[3 * CHP + tid];
        unsigned int kx = min(min(m0.x, m1.x), min(m2.x, m3.x));
        unsigned int ky = min(min(m0.y, m1.y), min(m2.y, m3.y));
        int j0 = ch * CHJ + 2 * tid;
        atomicMax(&g_colk[b * NP + j0],     ~kx);
        atomicMax(&g_colk[b * NP + j0 + 1], ~ky);
    }

    // ---- fused tail: last CTA of this batch reduces + resets ----
    __threadfence();
    if (tid == 0) {
        unsigned int old = atomicAdd(&g_done[b], 1u);
        s_last = (old == CTAS_PER_B - 1) ? 1u : 0u;
    }
    __syncthreads();
    if (s_last) {
        __threadfence();  // acquire: all batch-b key writes visible
        float sum = 0.f;
#pragma unroll
        for (int k = 0; k < NP / 128; k++) {   // 16 iters, 128 thr
            int idx = b * NP + k * 128 + tid;
            unsigned int rk = g_rowk[idx];
            unsigned int ck = g_colk[idx];
            sum += __uint_as_float(~rk) + __uint_as_float(~ck);
            g_rowk[idx] = 0u;   // reset for next graph replay
            g_colk[idx] = 0u;
        }
        __shared__ float red[128];
        red[tid] = sum;
        __syncthreads();
        for (int st = 64; st > 0; st >>= 1) {
            if (tid < st) red[tid] += red[tid + st];
            __syncthreads();
        }
        if (tid == 0) {
            out[b] = 0.5f * red[0] - 2.0f * (2.0f * NP);
            g_done[b] = 0u;     // reset counter
        }
    }
}

extern "C" void kernel_launch(void* const* d_in, const int* in_sizes, int n_in,
                              void* d_out, int out_size) {
    const float* mu_p = (const float*)d_in[0];
    const float* lv_p = (const float*)d_in[1];
    const float* mu_g = (const float*)d_in[2];
    const float* lv_g = (const float*)d_in[3];
    float* out = (float*)d_out;

    dim3 grid(NITILE, NB, NCH);  // 4 x 8 x 32 = 1024 CTAs
    ck_main<<<grid, 128>>>(mu_p, lv_p, mu_g, lv_g, out);
}